// round 5
// baseline (speedup 1.0000x reference)
#include <cuda_runtime.h>
#include <math.h>

#define BB 2
#define SS 2048
#define DIMD 512
#define HEADS 4
#define DH 128
#define CHUNK 16
#define NCHUNK 128
#define BH 8
#define DH2 16384
#define MAX_LR 0.01f
#define EPSV 1e-6f

// ---------------- scratch ----------------
__device__ float g_xnorm[BB*SS*DIMD];
__device__ float g_k[BH*NCHUNK*CHUNK*DH];
__device__ float g_v[BH*NCHUNK*CHUNK*DH];
__device__ float g_lr[BH*NCHUNK*CHUNK];
__device__ float g_mom[BH*NCHUNK];
__device__ float g_dec[BH*NCHUNK];

__device__ __forceinline__ float sigf(float x) { return 1.f / (1.f + __expf(-x)); }

// ------- packed f32x2 helpers -------
__device__ __forceinline__ unsigned long long fma2(unsigned long long a,
                                                   unsigned long long b,
                                                   unsigned long long c) {
    unsigned long long d;
    asm("fma.rn.f32x2 %0, %1, %2, %3;" : "=l"(d) : "l"(a), "l"(b), "l"(c));
    return d;
}
__device__ __forceinline__ unsigned long long dup2(float x) {
    unsigned long long d;
    unsigned int xi = __float_as_uint(x);
    asm("mov.b64 %0, {%1, %1};" : "=l"(d) : "r"(xi));
    return d;
}
__device__ __forceinline__ float2 unpk2(unsigned long long v) {
    unsigned int lo, hi;
    asm("mov.b64 {%0, %1}, %2;" : "=r"(lo), "=r"(hi) : "l"(v));
    return make_float2(__uint_as_float(lo), __uint_as_float(hi));
}

// ---------------- K1: RMSNorm + per-token lr ----------------
__global__ void k_rmsnorm(const float* __restrict__ seq,
                          const float* __restrict__ scale,
                          const float* __restrict__ Wstep) {
    int tok = blockIdx.x;
    int tid = threadIdx.x;
    int lane = tid & 31, warp = tid >> 5;
    __shared__ float red[4];
    __shared__ float redp[4][4];

    float4 v = ((const float4*)(seq + (size_t)tok * DIMD))[tid];
    float ss = v.x*v.x + v.y*v.y + v.z*v.z + v.w*v.w;
#pragma unroll
    for (int o = 16; o; o >>= 1) ss += __shfl_xor_sync(0xffffffffu, ss, o);
    if (lane == 0) red[warp] = ss;
    __syncthreads();
    float tot = red[0] + red[1] + red[2] + red[3];
    float inv = rsqrtf(tot * (1.f / DIMD) + EPSV);

    float4 sc = ((const float4*)scale)[tid];
    float4 xn = make_float4(v.x*inv*sc.x, v.y*inv*sc.y, v.z*inv*sc.z, v.w*inv*sc.w);
    ((float4*)(g_xnorm + (size_t)tok * DIMD))[tid] = xn;

    int d0 = tid * 4;
    float4 wa = ((const float4*)Wstep)[d0 + 0];
    float4 wb = ((const float4*)Wstep)[d0 + 1];
    float4 wc = ((const float4*)Wstep)[d0 + 2];
    float4 wd = ((const float4*)Wstep)[d0 + 3];
    float p0 = xn.x*wa.x + xn.y*wb.x + xn.z*wc.x + xn.w*wd.x;
    float p1 = xn.x*wa.y + xn.y*wb.y + xn.z*wc.y + xn.w*wd.y;
    float p2 = xn.x*wa.z + xn.y*wb.z + xn.z*wc.z + xn.w*wd.z;
    float p3 = xn.x*wa.w + xn.y*wb.w + xn.z*wc.w + xn.w*wd.w;
#pragma unroll
    for (int o = 16; o; o >>= 1) {
        p0 += __shfl_xor_sync(0xffffffffu, p0, o);
        p1 += __shfl_xor_sync(0xffffffffu, p1, o);
        p2 += __shfl_xor_sync(0xffffffffu, p2, o);
        p3 += __shfl_xor_sync(0xffffffffu, p3, o);
    }
    if (lane == 0) { redp[warp][0] = p0; redp[warp][1] = p1; redp[warp][2] = p2; redp[warp][3] = p3; }
    __syncthreads();
    if (tid < 4) {
        float p = redp[0][tid] + redp[1][tid] + redp[2][tid] + redp[3][tid];
        float lrv = MAX_LR * sigf(p);
        int b = tok / SS, s = tok % SS;
        int t = s / CHUNK, c = s % CHUNK;
        g_lr[(((b * HEADS + tid) * NCHUNK + t) * CHUNK) + c] = lrv;
    }
}

// ---------------- K2: chunk means -> mom/dec ----------------
__global__ void k_chunkstats(const float* __restrict__ Wmom,
                             const float* __restrict__ Wdec) {
    int blk = blockIdx.x;
    int b = blk / NCHUNK, t = blk % NCHUNK;
    int tid = threadIdx.x;
    int lane = tid & 31, warp = tid >> 5;
    __shared__ float redp[4][8];

    int d0 = tid * 4;
    const float* xb = g_xnorm + ((size_t)(b * SS + t * CHUNK)) * DIMD;
    float4 m = make_float4(0.f, 0.f, 0.f, 0.f);
#pragma unroll
    for (int c = 0; c < CHUNK; c++) {
        float4 v = *(const float4*)(xb + (size_t)c * DIMD + d0);
        m.x += v.x; m.y += v.y; m.z += v.z; m.w += v.w;
    }
    m.x *= (1.f/CHUNK); m.y *= (1.f/CHUNK); m.z *= (1.f/CHUNK); m.w *= (1.f/CHUNK);

    float4 ma = ((const float4*)Wmom)[d0 + 0];
    float4 mb = ((const float4*)Wmom)[d0 + 1];
    float4 mc = ((const float4*)Wmom)[d0 + 2];
    float4 md = ((const float4*)Wmom)[d0 + 3];
    float4 da = ((const float4*)Wdec)[d0 + 0];
    float4 db = ((const float4*)Wdec)[d0 + 1];
    float4 dc = ((const float4*)Wdec)[d0 + 2];
    float4 dd = ((const float4*)Wdec)[d0 + 3];

    float p[8];
    p[0] = m.x*ma.x + m.y*mb.x + m.z*mc.x + m.w*md.x;
    p[1] = m.x*ma.y + m.y*mb.y + m.z*mc.y + m.w*md.y;
    p[2] = m.x*ma.z + m.y*mb.z + m.z*mc.z + m.w*md.z;
    p[3] = m.x*ma.w + m.y*mb.w + m.z*mc.w + m.w*md.w;
    p[4] = m.x*da.x + m.y*db.x + m.z*dc.x + m.w*dd.x;
    p[5] = m.x*da.y + m.y*db.y + m.z*dc.y + m.w*dd.y;
    p[6] = m.x*da.z + m.y*db.z + m.z*dc.z + m.w*dd.z;
    p[7] = m.x*da.w + m.y*db.w + m.z*dc.w + m.w*dd.w;
#pragma unroll
    for (int i = 0; i < 8; i++) {
#pragma unroll
        for (int o = 16; o; o >>= 1) p[i] += __shfl_xor_sync(0xffffffffu, p[i], o);
    }
    if (lane == 0) {
#pragma unroll
        for (int i = 0; i < 8; i++) redp[warp][i] = p[i];
    }
    __syncthreads();
    if (tid < 8) {
        float s = redp[0][tid] + redp[1][tid] + redp[2][tid] + redp[3][tid];
        float sv = sigf(s);
        int h = tid & 3;
        if (tid < 4) g_mom[(b * HEADS + h) * NCHUNK + t] = sv;
        else         g_dec[(b * HEADS + h) * NCHUNK + t] = sv;
    }
}

// ---------------- K3: kv projection (tiled, f32x2) ----------------
#define KV_ROWS 32
__global__ void __launch_bounds__(256, 2) k_kvproj(const float* __restrict__ Wkv) {
    extern __shared__ float xs[];
    int rg  = blockIdx.x & 127;
    int cgp = blockIdx.x >> 7;
    int tid = threadIdx.x;

    const float4* src = (const float4*)(g_xnorm + (size_t)rg * KV_ROWS * DIMD);
#pragma unroll
    for (int i = tid; i < KV_ROWS * DIMD / 4; i += 256) ((float4*)xs)[i] = src[i];
    __syncthreads();

    int rs = tid >> 6;
    int cg = tid & 63;
    int r0 = rs * 8;
    int col = cgp * 256 + cg * 4;

    unsigned long long acc[8][2];
#pragma unroll
    for (int r = 0; r < 8; r++) { acc[r][0] = 0ull; acc[r][1] = 0ull; }

    const float* wbase = Wkv + col;
#pragma unroll 2
    for (int dt = 0; dt < DIMD; dt += 4) {
        float4 xv[8];
#pragma unroll
        for (int r = 0; r < 8; r++) xv[r] = *(const float4*)&xs[(r0 + r) * DIMD + dt];
#pragma unroll
        for (int dd = 0; dd < 4; dd++) {
            ulonglong2 wl = *(const ulonglong2*)(wbase + (size_t)(dt + dd) * 1024);
#pragma unroll
            for (int r = 0; r < 8; r++) {
                float xc = (dd == 0) ? xv[r].x : (dd == 1) ? xv[r].y : (dd == 2) ? xv[r].z : xv[r].w;
                unsigned long long kk = dup2(xc);
                acc[r][0] = fma2(kk, wl.x, acc[r][0]);
                acc[r][1] = fma2(kk, wl.y, acc[r][1]);
            }
        }
    }

    int isv = (col >= 512);
    int c2 = col - isv * 512;
    int h = c2 >> 7, j = c2 & 127;
    float* base = (isv ? g_v : g_k);
#pragma unroll
    for (int r = 0; r < 8; r++) {
        int tg = rg * KV_ROWS + r0 + r;
        int b = tg >> 11, s = tg & 2047;
        float* dst = base + ((size_t)((b * HEADS + h) * SS + s)) * DH + j;
        *(ulonglong2*)dst = make_ulonglong2(acc[r][0], acc[r][1]);
    }
}

// ---------------- K4: per-chunk gradients (4 chunks/CTA, 4x4 reg tiles) ----------------
#define CPG 4
#define MROWS 64
#define WPITCH 140

// acc[c][j] += sum_d A[c0+c][d] * W[d][j0+j]   (A rows broadcast, W rows conflict-free)
__device__ __forceinline__ void gemm64(const float* __restrict__ A,
                                       const float* __restrict__ W,
                                       int c0, int j0,
                                       unsigned long long acc[4][2]) {
#pragma unroll
    for (int i = 0; i < 4; i++) { acc[i][0] = 0ull; acc[i][1] = 0ull; }
#pragma unroll 2
    for (int dq = 0; dq < DH; dq += 4) {
        float4 ar[4];
#pragma unroll
        for (int i = 0; i < 4; i++) ar[i] = *(const float4*)&A[(c0 + i) * DH + dq];
#pragma unroll
        for (int dd = 0; dd < 4; dd++) {
            ulonglong2 w = *(const ulonglong2*)&W[(dq + dd) * WPITCH + j0];
#pragma unroll
            for (int i = 0; i < 4; i++) {
                float av = (dd == 0) ? ar[i].x : (dd == 1) ? ar[i].y : (dd == 2) ? ar[i].z : ar[i].w;
                unsigned long long aa = dup2(av);
                acc[i][0] = fma2(aa, w.x, acc[i][0]);
                acc[i][1] = fma2(aa, w.y, acc[i][1]);
            }
        }
    }
}

// out[d1+r][d2+c] = sum_cc Arows[crow][d1+r] * Grows[crow][d2+c], 8x4 tile
__device__ __forceinline__ void outer16(const float* __restrict__ Arows,
                                        const float* __restrict__ Grows,
                                        int crowbase, int d1, int d2,
                                        float* __restrict__ o) {
    unsigned long long acc[4][4];
#pragma unroll
    for (int rp = 0; rp < 4; rp++)
#pragma unroll
        for (int cc = 0; cc < 4; cc++) acc[rp][cc] = 0ull;
#pragma unroll
    for (int cc2 = 0; cc2 < CHUNK; cc2++) {
        int crow = crowbase + cc2;
        ulonglong2 a01 = *(const ulonglong2*)&Arows[crow * DH + d1];
        ulonglong2 a23 = *(const ulonglong2*)&Arows[crow * DH + d1 + 4];
        float4 gv = *(const float4*)&Grows[crow * DH + d2];
        unsigned long long g0 = dup2(gv.x), g1 = dup2(gv.y),
                           g2 = dup2(gv.z), g3 = dup2(gv.w);
        acc[0][0] = fma2(a01.x, g0, acc[0][0]);
        acc[0][1] = fma2(a01.x, g1, acc[0][1]);
        acc[0][2] = fma2(a01.x, g2, acc[0][2]);
        acc[0][3] = fma2(a01.x, g3, acc[0][3]);
        acc[1][0] = fma2(a01.y, g0, acc[1][0]);
        acc[1][1] = fma2(a01.y, g1, acc[1][1]);
        acc[1][2] = fma2(a01.y, g2, acc[1][2]);
        acc[1][3] = fma2(a01.y, g3, acc[1][3]);
        acc[2][0] = fma2(a23.x, g0, acc[2][0]);
        acc[2][1] = fma2(a23.x, g1, acc[2][1]);
        acc[2][2] = fma2(a23.x, g2, acc[2][2]);
        acc[2][3] = fma2(a23.x, g3, acc[2][3]);
        acc[3][0] = fma2(a23.y, g0, acc[3][0]);
        acc[3][1] = fma2(a23.y, g1, acc[3][1]);
        acc[3][2] = fma2(a23.y, g2, acc[3][2]);
        acc[3][3] = fma2(a23.y, g3, acc[3][3]);
    }
#pragma unroll
    for (int rp = 0; rp < 4; rp++) {
        float2 u0 = unpk2(acc[rp][0]), u1 = unpk2(acc[rp][1]);
        float2 u2 = unpk2(acc[rp][2]), u3 = unpk2(acc[rp][3]);
        int rl = d1 + 2 * rp;
        *(float4*)(o + (size_t)rl * DH + d2)       = make_float4(u0.x, u1.x, u2.x, u3.x);
        *(float4*)(o + (size_t)(rl + 1) * DH + d2) = make_float4(u0.y, u1.y, u2.y, u3.y);
    }
}

__global__ void __launch_bounds__(512, 1)
k_grad(const float* __restrict__ w0g_all, const float* __restrict__ w1g_all,
       float* __restrict__ out) {
    extern __shared__ float sm[];
    float* ws  = sm;                        // 128*140 = 17920
    float* ks  = ws + 128 * WPITCH;         // 64*128 = 8192
    float* vs  = ks + MROWS * DH;           // v -> Gn
    float* as_ = vs + MROWS * DH;           // silu(h)
    float* ss  = as_ + MROWS * DH;          // sigma(h) -> dhn
    float* lrs = ss + MROWS * DH;           // 64

    int bh = blockIdx.x >> 5;
    int tg = blockIdx.x & 31;
    int t0 = tg * CPG;
    int tid = threadIdx.x;

    // ---- load k, v, lr, w0 ----
    const float4* kg = (const float4*)(g_k + ((size_t)(bh * NCHUNK + t0)) * (CHUNK * DH));
    const float4* vg = (const float4*)(g_v + ((size_t)(bh * NCHUNK + t0)) * (CHUNK * DH));
    for (int i = tid; i < MROWS * DH / 4; i += 512) {
        ((float4*)ks)[i] = kg[i];
        ((float4*)vs)[i] = vg[i];
    }
    if (tid < MROWS) lrs[tid] = g_lr[(bh * NCHUNK + t0) * CHUNK + tid];
    const float4* w0g4 = (const float4*)(w0g_all + (size_t)bh * DH2);
    for (int i = tid; i < 4096; i += 512) {
        int row = i >> 5, col = (i & 31) * 4;
        *(float4*)&ws[row * WPITCH + col] = w0g4[i];
    }
    __syncthreads();

    int ty = tid >> 5, tx = tid & 31;
    int c0 = ty * 4, j0 = tx * 4;
    unsigned long long acc[4][2];

    // ---- GEMM A: h = k @ w0 ; store sigma(h), silu(h) ----
    gemm64(ks, ws, c0, j0, acc);
#pragma unroll
    for (int i = 0; i < 4; i++) {
        float2 h01 = unpk2(acc[i][0]), h23 = unpk2(acc[i][1]);
        float s0 = sigf(h01.x), s1 = sigf(h01.y), s2 = sigf(h23.x), s3 = sigf(h23.y);
        *(float4*)&ss[(c0 + i) * DH + j0]  = make_float4(s0, s1, s2, s3);
        *(float4*)&as_[(c0 + i) * DH + j0] = make_float4(h01.x * s0, h01.y * s1, h23.x * s2, h23.y * s3);
    }
    __syncthreads();

    // ---- load w1 ----
    const float4* w1g4 = (const float4*)(w1g_all + (size_t)bh * DH2);
    for (int i = tid; i < 4096; i += 512) {
        int row = i >> 5, col = (i & 31) * 4;
        *(float4*)&ws[row * WPITCH + col] = w1g4[i];
    }
    __syncthreads();

    // ---- GEMM B: pred = a @ w1 ; Gn = f*(v - pred) into vs ----
    gemm64(as_, ws, c0, j0, acc);
#pragma unroll
    for (int i = 0; i < 4; i++) {
        float f = 2.f * lrs[c0 + i] * (1.f / DH);
        float2 p01 = unpk2(acc[i][0]), p23 = unpk2(acc[i][1]);
        float4 vv = *(const float4*)&vs[(c0 + i) * DH + j0];
        *(float4*)&vs[(c0 + i) * DH + j0] =
            make_float4(f * (vv.x - p01.x), f * (vv.y - p01.y),
                        f * (vv.z - p23.x), f * (vv.w - p23.y));
    }
    __syncthreads();

    // ---- load w1^T (coalesced read, scattered smem store) ----
    {
        const float* w1g = w1g_all + (size_t)bh * DH2;
        for (int i = tid; i < DH2; i += 512) {
            ws[(i & 127) * WPITCH + (i >> 7)] = w1g[i];
        }
    }
    __syncthreads();

    int d1 = (tid >> 5) * 8, d2 = (tid & 31) * 4;

    // ---- G1: s1 = a^T @ Gn per chunk (doesn't touch ws/ss) ----
#pragma unroll
    for (int ch = 0; ch < CPG; ch++) {
        float* o1 = out + ((size_t)((BH + bh) * NCHUNK + t0 + ch)) * DH2;
        outer16(as_, vs, ch * CHUNK, d1, d2, o1);
    }

    // ---- GEMM C: dA = Gn @ w1^T ; dhn = dA * (s + a*(1-s)) into ss ----
    gemm64(vs, ws, c0, j0, acc);
#pragma unroll
    for (int i = 0; i < 4; i++) {
        float2 d01 = unpk2(acc[i][0]), d23 = unpk2(acc[i][1]);
        float4 sv = *(const float4*)&ss[(c0 + i) * DH + j0];
        float4 av = *(const float4*)&as_[(c0 + i) * DH + j0];
        d01.x *= sv.x + av.x * (1.f - sv.x);
        d01.y *= sv.y + av.y * (1.f - sv.y);
        d23.x *= sv.z + av.z * (1.f - sv.z);
        d23.y *= sv.w + av.w * (1.f - sv.w);
        *(float4*)&ss[(c0 + i) * DH + j0] = make_float4(d01.x, d01.y, d23.x, d23.y);
    }
    __syncthreads();

    // ---- G0: s0 = k^T @ dhn per chunk ----
#pragma unroll
    for (int ch = 0; ch < CPG; ch++) {
        float* o0 = out + ((size_t)(bh * NCHUNK + t0 + ch)) * DH2;
        outer16(ks, ss, ch * CHUNK, d1, d2, o0);
    }
}

// ---------------- K5: fused momentum + decay scan ----------------
__global__ void k_scan(float* __restrict__ out) {
    __shared__ float moms[NCHUNK], decs[NCHUNK];
    int blk = blockIdx.x;
    int sbh = blk >> 5;
    int eb  = blk & 31;
    int bh  = sbh & 7;
    int tid = threadIdx.x;
    if (tid < NCHUNK) {
        moms[tid] = g_mom[bh * NCHUNK + tid];
        decs[tid] = 1.f - g_dec[bh * NCHUNK + tid];
    }
    __syncthreads();
    size_t base = (size_t)sbh * NCHUNK * DH2 + (size_t)eb * 512 + tid * 4;
    float4 m = make_float4(0.f, 0.f, 0.f, 0.f);
    float4 u = make_float4(0.f, 0.f, 0.f, 0.f);
#pragma unroll 4
    for (int t = 0; t < NCHUNK; t++) {
        size_t idx = base + (size_t)t * DH2;
        float4 sv = *(float4*)(out + idx);
        float mo = moms[t], de = decs[t];
        m.x = mo * m.x + sv.x;  m.y = mo * m.y + sv.y;
        m.z = mo * m.z + sv.z;  m.w = mo * m.w + sv.w;
        u.x = de * u.x + m.x;   u.y = de * u.y + m.y;
        u.z = de * u.z + m.z;   u.w = de * u.w + m.w;
        *(float4*)(out + idx) = u;
    }
}

// ---------------- launch ----------------
extern "C" void kernel_launch(void* const* d_in, const int* in_sizes, int n_in,
                              void* d_out, int out_size) {
    const float* seq   = (const float*)d_in[0];
    const float* scale = (const float*)d_in[1];
    const float* Wkv   = (const float*)d_in[2];
    const float* Wstep = (const float*)d_in[3];
    const float* Wmom  = (const float*)d_in[4];
    const float* Wdec  = (const float*)d_in[5];
    const float* w0    = (const float*)d_in[6];
    const float* w1    = (const float*)d_in[7];
    float* out = (float*)d_out;

    const int GRAD_SMEM = (128 * WPITCH + 4 * MROWS * DH + 64) * 4;  // 203008 B
    const int KV_SMEM = KV_ROWS * DIMD * 4;
    cudaFuncSetAttribute(k_grad, cudaFuncAttributeMaxDynamicSharedMemorySize, GRAD_SMEM);
    cudaFuncSetAttribute(k_kvproj, cudaFuncAttributeMaxDynamicSharedMemorySize, KV_SMEM);

    k_rmsnorm<<<BB * SS, 128>>>(seq, scale, Wstep);
    k_chunkstats<<<BB * NCHUNK, 128>>>(Wmom, Wdec);
    k_kvproj<<<512, 256, KV_SMEM>>>(Wkv);
    k_grad<<<BH * (NCHUNK / CPG), 512, GRAD_SMEM>>>(w0, w1, out);
    k_scan<<<512, 128>>>(out);
}